// round 17
// baseline (speedup 1.0000x reference)
#include <cuda_runtime.h>
#include <cuda_bf16.h>
#include <cstdint>

#define BB 8
#define SS 2048
#define DIN 1024
#define DOUT 64

// Scratch (device globals: no allocation allowed)
__device__ unsigned char g_mask[BB * SS];
// Pre-converted activations (written by proj_mma epilogue):
__device__ __align__(16) __nv_bfloat16 g_qb[BB * SS * DOUT];   // q * 1/sqrt(S), bf16
__device__ __align__(16) __nv_bfloat16 g_kb[BB * SS * DOUT];   // k, bf16
__device__ __align__(16) __nv_bfloat16 g_vth[BB * DOUT * SS];  // v hi, transposed [b][d][s]
__device__ __align__(16) __nv_bfloat16 g_vtl[BB * DOUT * SS];  // v lo, transposed
// W transposed + bf16 hi/lo split: [w][n][k]
__device__ __align__(16) __nv_bfloat16 g_wh[3 * DOUT * DIN];
__device__ __align__(16) __nv_bfloat16 g_wl[3 * DOUT * DIN];

// ---------------------------------------------------------------------------
// Helpers
// ---------------------------------------------------------------------------
__device__ __forceinline__ uint32_t bpack(__nv_bfloat16 a, __nv_bfloat16 b) {
    return ((uint32_t)__bfloat16_as_ushort(b) << 16) | __bfloat16_as_ushort(a);
}

// mma.sync m16n8k16 row.col f32 += bf16*bf16 (baseline PTX ISA, sm_80+)
__device__ __forceinline__ void mma16816(float* c, const uint32_t* a, const uint32_t* b) {
    asm volatile(
        "mma.sync.aligned.m16n8k16.row.col.f32.bf16.bf16.f32 "
        "{%0,%1,%2,%3}, {%4,%5,%6,%7}, {%8,%9}, {%0,%1,%2,%3};"
        : "+f"(c[0]), "+f"(c[1]), "+f"(c[2]), "+f"(c[3])
        : "r"(a[0]), "r"(a[1]), "r"(a[2]), "r"(a[3]), "r"(b[0]), "r"(b[1]));
}

// exp(x) for x <= 0 on the FMA/ALU pipes (no MUFU). rel err ~2e-6.
__device__ __forceinline__ float exp_fma(float x) {
    x = fmaxf(x, -87.0f);
    float t  = fmaf(x, 1.4426950408889634f, 12582912.0f);
    float fi = t - 12582912.0f;
    float f  = fmaf(x, 1.4426950408889634f, -fi);
    float p  = 0.0013333558f;
    p = fmaf(p, f, 0.0096181291f);
    p = fmaf(p, f, 0.0555041087f);
    p = fmaf(p, f, 0.2402265069f);
    p = fmaf(p, f, 0.6931471806f);
    p = fmaf(p, f, 1.0f);
    int ei = (__float_as_int(t) & 0x7FFFFF) - 0x400000;
    return __int_as_float((ei + 127) << 23) * p;
}

// ---------------------------------------------------------------------------
// W prep: transpose + bf16 hi/lo split. 768 blocks -> 1 element per thread.
// ---------------------------------------------------------------------------
__global__ void w_convert(const float* __restrict__ Wq, const float* __restrict__ Wk,
                          const float* __restrict__ Wv) {
    int i = blockIdx.x * blockDim.x + threadIdx.x;
    if (i >= 3 * DIN * DOUT) return;
    int w = i / (DIN * DOUT);
    int r = i - w * (DIN * DOUT);
    int k = r / DOUT, n = r % DOUT;
    const float* W = (w == 0) ? Wq : (w == 1) ? Wk : Wv;
    float x = W[r];
    __nv_bfloat16 h = __float2bfloat16(x);
    __nv_bfloat16 l = __float2bfloat16(x - __bfloat162float(h));
    g_wh[w * DIN * DOUT + n * DIN + k] = h;
    g_wl[w * DIN * DOUT + n * DIN + k] = l;
}

// ---------------------------------------------------------------------------
// HMMA QKV projection (bf16x3 split). 128 CTAs x 256 thr, M_tile=128.
// Epilogue emits pre-converted bf16 activations (q scaled, v split+transposed).
// CTA 0 folds in mask normalization.
// ---------------------------------------------------------------------------
#define ASTR 72
#define SM_AH 0
#define SM_AL (128 * ASTR * 2)
#define SM_W  (2 * 128 * ASTR * 2)
#define SM_BIAS (SM_W + 6 * 64 * ASTR * 2)
#define PJ_SMEM (SM_BIAS + 768)

__global__ void __launch_bounds__(256) proj_mma(
    const float* __restrict__ A, const unsigned char* __restrict__ maskp,
    const float* __restrict__ bq, const float* __restrict__ bk, const float* __restrict__ bv)
{
    extern __shared__ unsigned char smem[];
    __nv_bfloat16* AH = (__nv_bfloat16*)(smem + SM_AH);
    __nv_bfloat16* AL = (__nv_bfloat16*)(smem + SM_AL);
    float* biasS = (float*)(smem + SM_BIAS);

    int tid = threadIdx.x, wid = tid >> 5, lane = tid & 31;
    int g = lane >> 2, t = lane & 3;
    int m0 = blockIdx.x * 128;
    int r0 = wid * 16;

    if (blockIdx.x == 0) {
        __shared__ int s_off, s_al;
        if (tid == 0) { s_off = 0; s_al = 0; }
        __syncthreads();
        int lo = 0, la = 0;
        for (int i = tid; i < BB * SS; i += 256) {
            unsigned char v = maskp[i];
            if (v) { if (i & 3) lo++; else la++; }
        }
        if (lo) atomicAdd(&s_off, lo);
        if (la) atomicAdd(&s_al, la);
        __syncthreads();
        int kind = 0;
        if (s_off == 0 && s_al > 0) kind = 1;
        else if (s_al == 0 && s_off > 0) kind = 2;
        for (int i = tid; i < BB * SS; i += 256) {
            unsigned char m;
            if (kind == 1)      m = (((const int*)(const void*)maskp)[i] != 0);
            else if (kind == 2) m = (((const float*)(const void*)maskp)[i] != 0.0f);
            else                m = (maskp[i] != 0);
            g_mask[i] = m;
        }
    }

    if (tid < 64) {
        biasS[tid]       = bq[tid];
        biasS[tid + 64]  = bk[tid];
        biasS[tid + 128] = bv[tid];
    }

    float acc[3][8][4];
    #pragma unroll
    for (int w = 0; w < 3; w++)
        #pragma unroll
        for (int nb = 0; nb < 8; nb++)
            #pragma unroll
            for (int i = 0; i < 4; i++) acc[w][nb][i] = 0.0f;

    for (int c = 0; c < 16; c++) {
        int k0 = c * 64;
        __syncthreads();

        #pragma unroll
        for (int it = 0; it < 8; it++) {
            int idx = it * 256 + tid;
            int row = idx >> 4;
            int col = (idx & 15) << 2;
            float4 v = *(const float4*)(A + (size_t)(m0 + row) * DIN + k0 + col);
            __nv_bfloat16 h0 = __float2bfloat16(v.x), h1 = __float2bfloat16(v.y);
            __nv_bfloat16 h2 = __float2bfloat16(v.z), h3 = __float2bfloat16(v.w);
            __nv_bfloat16 l0 = __float2bfloat16(v.x - __bfloat162float(h0));
            __nv_bfloat16 l1 = __float2bfloat16(v.y - __bfloat162float(h1));
            __nv_bfloat16 l2 = __float2bfloat16(v.z - __bfloat162float(h2));
            __nv_bfloat16 l3 = __float2bfloat16(v.w - __bfloat162float(h3));
            uint2 hv = { bpack(h0, h1), bpack(h2, h3) };
            uint2 lv = { bpack(l0, l1), bpack(l2, l3) };
            *(uint2*)(AH + row * ASTR + col) = hv;
            *(uint2*)(AL + row * ASTR + col) = lv;
        }

        #pragma unroll
        for (int it = 0; it < 24; it++) {
            int i = it * 256 + tid;
            int tile = i >> 10;
            int word = i & 1023;
            int n = word >> 4;
            int kk = (word & 15) << 2;
            const __nv_bfloat16* src = (tile & 1) ? g_wl : g_wh;
            uint2 d = *(const uint2*)(src + (size_t)(tile >> 1) * (DIN * DOUT) + n * DIN + k0 + kk);
            *(uint2*)((__nv_bfloat16*)(smem + SM_W) + tile * (64 * ASTR) + n * ASTR + kk) = d;
        }
        __syncthreads();

        #pragma unroll
        for (int ks = 0; ks < 4; ks++) {
            int kb = ks * 16;
            uint32_t ah[4], al[4];
            ah[0] = *(const uint32_t*)(AH + (r0 + g)     * ASTR + kb + t * 2);
            ah[1] = *(const uint32_t*)(AH + (r0 + g + 8) * ASTR + kb + t * 2);
            ah[2] = *(const uint32_t*)(AH + (r0 + g)     * ASTR + kb + t * 2 + 8);
            ah[3] = *(const uint32_t*)(AH + (r0 + g + 8) * ASTR + kb + t * 2 + 8);
            al[0] = *(const uint32_t*)(AL + (r0 + g)     * ASTR + kb + t * 2);
            al[1] = *(const uint32_t*)(AL + (r0 + g + 8) * ASTR + kb + t * 2);
            al[2] = *(const uint32_t*)(AL + (r0 + g)     * ASTR + kb + t * 2 + 8);
            al[3] = *(const uint32_t*)(AL + (r0 + g + 8) * ASTR + kb + t * 2 + 8);

            #pragma unroll
            for (int w = 0; w < 3; w++) {
                const __nv_bfloat16* WH = (__nv_bfloat16*)(smem + SM_W) + (w * 2)     * (64 * ASTR);
                const __nv_bfloat16* WL = (__nv_bfloat16*)(smem + SM_W) + (w * 2 + 1) * (64 * ASTR);
                #pragma unroll
                for (int nb = 0; nb < 8; nb++) {
                    int n = nb * 8 + g;
                    uint32_t bh[2], bl[2];
                    bh[0] = *(const uint32_t*)(WH + n * ASTR + kb + t * 2);
                    bh[1] = *(const uint32_t*)(WH + n * ASTR + kb + t * 2 + 8);
                    bl[0] = *(const uint32_t*)(WL + n * ASTR + kb + t * 2);
                    bl[1] = *(const uint32_t*)(WL + n * ASTR + kb + t * 2 + 8);
                    mma16816(acc[w][nb], ah, bh);
                    mma16816(acc[w][nb], ah, bl);
                    mma16816(acc[w][nb], al, bh);
                }
            }
        }
    }

    // ---- Epilogue: bias add, convert to bf16, q scaled, v split+transposed ----
    {
        const float qs = rsqrtf((float)SS);
        int row_a = m0 + r0 + g;
        int row_b = row_a + 8;
        int bb = row_a >> 11;
        int sa = row_a & (SS - 1), sb = sa + 8;
        #pragma unroll
        for (int nb = 0; nb < 8; nb++) {
            int col = nb * 8 + t * 2;
            // q (scaled)
            float q0 = (acc[0][nb][0] + biasS[col])     * qs;
            float q1 = (acc[0][nb][1] + biasS[col + 1]) * qs;
            float q2 = (acc[0][nb][2] + biasS[col])     * qs;
            float q3 = (acc[0][nb][3] + biasS[col + 1]) * qs;
            *(uint32_t*)(g_qb + (size_t)row_a * DOUT + col) =
                bpack(__float2bfloat16(q0), __float2bfloat16(q1));
            *(uint32_t*)(g_qb + (size_t)row_b * DOUT + col) =
                bpack(__float2bfloat16(q2), __float2bfloat16(q3));
            // k
            float k0v = acc[1][nb][0] + biasS[64 + col];
            float k1v = acc[1][nb][1] + biasS[64 + col + 1];
            float k2v = acc[1][nb][2] + biasS[64 + col];
            float k3v = acc[1][nb][3] + biasS[64 + col + 1];
            *(uint32_t*)(g_kb + (size_t)row_a * DOUT + col) =
                bpack(__float2bfloat16(k0v), __float2bfloat16(k1v));
            *(uint32_t*)(g_kb + (size_t)row_b * DOUT + col) =
                bpack(__float2bfloat16(k2v), __float2bfloat16(k3v));
            // v: hi/lo split, transposed [b][d][s]
            float v0 = acc[2][nb][0] + biasS[128 + col];
            float v1 = acc[2][nb][1] + biasS[128 + col + 1];
            float v2 = acc[2][nb][2] + biasS[128 + col];
            float v3 = acc[2][nb][3] + biasS[128 + col + 1];
            __nv_bfloat16 vh0 = __float2bfloat16(v0), vh1 = __float2bfloat16(v1);
            __nv_bfloat16 vh2 = __float2bfloat16(v2), vh3 = __float2bfloat16(v3);
            __nv_bfloat16 vl0 = __float2bfloat16(v0 - __bfloat162float(vh0));
            __nv_bfloat16 vl1 = __float2bfloat16(v1 - __bfloat162float(vh1));
            __nv_bfloat16 vl2 = __float2bfloat16(v2 - __bfloat162float(vh2));
            __nv_bfloat16 vl3 = __float2bfloat16(v3 - __bfloat162float(vh3));
            size_t c0 = ((size_t)bb * DOUT + col) * SS;
            size_t c1 = ((size_t)bb * DOUT + col + 1) * SS;
            g_vth[c0 + sa] = vh0;  g_vtl[c0 + sa] = vl0;
            g_vth[c1 + sa] = vh1;  g_vtl[c1 + sa] = vl1;
            g_vth[c0 + sb] = vh2;  g_vtl[c0 + sb] = vl2;
            g_vth[c1 + sb] = vh3;  g_vtl[c1 + sb] = vl3;
        }
    }
}

// ---------------------------------------------------------------------------
// HMMA flash attention, software-pipelined: 2-buffer dynamic smem + register
// prefetch. One __syncthreads per chunk; K/V/mask gmem latency overlaps MMA
// compute. Q/K plain bf16 single-term S; PV bf16x3 split; exp on FMA pipe.
// 128 CTAs (16 per batch) x 256 thr. Warp owns 16 query rows.
// ---------------------------------------------------------------------------
#define KSTR 72
#define BUFE (64 * KSTR)                       // bf16 elems per tile
#define ATT_SMEM (2 * 3 * BUFE * 2)            // 55296 bytes

__global__ void __launch_bounds__(256) attn_mma(float* __restrict__ out)
{
    extern __shared__ __nv_bfloat16 dyn[];
    __shared__ unsigned char maskS[2][64];

    int tid = threadIdx.x, wid = tid >> 5, lane = tid & 31;
    int g = lane >> 2, t = lane & 3;
    int b = blockIdx.x >> 4;
    int q0 = (blockIdx.x & 15) * 128;
    int qrow = q0 + wid * 16 + g;

    // Q fragments (already scaled bf16 in gmem)
    uint32_t qh[4][4];
    {
        const __nv_bfloat16* gq = g_qb + ((size_t)b * SS + qrow) * DOUT;
        #pragma unroll
        for (int ks = 0; ks < 4; ks++)
            #pragma unroll
            for (int hh = 0; hh < 2; hh++)
                #pragma unroll
                for (int rr = 0; rr < 2; rr++)
                    qh[ks][hh * 2 + rr] = *(const uint32_t*)(gq + (size_t)rr * 8 * DOUT +
                                                             ks * 16 + hh * 8 + 2 * t);
    }

    // Per-thread prefetch staging registers
    uint2 pk[4];
    uint32_t pvh[8], pvl[8];
    unsigned char pm = 0;

    // Fill-index precompute (constant across chunks)
    const int kkey = tid >> 4;                 // K: key row handled 4x (it*... no: below)
    const int kdp = (tid & 15) << 2;
    const int vd = tid >> 5;                   // V: d base handled 8x via +32*it? no: below
    const int vkp = (tid & 31) << 1;

    // load chunk (gmem -> regs)
    auto load_chunk = [&](int kb0) {
        #pragma unroll
        for (int it = 0; it < 4; it++) {
            int key = (it * 256 + tid) >> 4;
            pk[it] = *(const uint2*)(g_kb + ((size_t)b * SS + kb0 + key) * DOUT + kdp);
        }
        #pragma unroll
        for (int it = 0; it < 8; it++) {
            int d = (it * 256 + tid) >> 5;
            size_t go = ((size_t)b * DOUT + d) * SS + kb0 + vkp;
            pvh[it] = *(const uint32_t*)(g_vth + go);
            pvl[it] = *(const uint32_t*)(g_vtl + go);
        }
        if (tid < 64) pm = g_mask[b * SS + kb0 + tid];
    };
    // store regs -> smem buffer bi
    auto store_chunk = [&](int bi) {
        __nv_bfloat16* K  = dyn + bi * 3 * BUFE;
        __nv_bfloat16* Vh = K + BUFE;
        __nv_bfloat16* Vl = K + 2 * BUFE;
        #pragma unroll
        for (int it = 0; it < 4; it++) {
            int key = (it * 256 + tid) >> 4;
            *(uint2*)(K + key * KSTR + kdp) = pk[it];
        }
        #pragma unroll
        for (int it = 0; it < 8; it++) {
            int d = (it * 256 + tid) >> 5;
            *(uint32_t*)(Vh + d * KSTR + vkp) = pvh[it];
            *(uint32_t*)(Vl + d * KSTR + vkp) = pvl[it];
        }
        if (tid < 64) maskS[bi][tid] = pm;
    };

    float Ov[8][4];
    #pragma unroll
    for (int nb = 0; nb < 8; nb++)
        #pragma unroll
        for (int i = 0; i < 4; i++) Ov[nb][i] = 0.0f;
    float m_g = -1e30f, m_g8 = -1e30f, l_g = 0.0f, l_g8 = 0.0f;

    // Prologue: stage chunk 0
    load_chunk(0);
    store_chunk(0);
    __syncthreads();

    for (int c = 0; c < 32; c++) {
        // Prefetch next chunk into registers (overlaps with compute below)
        if (c + 1 < 32) load_chunk((c + 1) * 64);

        const __nv_bfloat16* Ksh = dyn + (c & 1) * 3 * BUFE;
        const __nv_bfloat16* Vsh = Ksh + BUFE;
        const __nv_bfloat16* Vsl = Ksh + 2 * BUFE;
        const unsigned char* mS = maskS[c & 1];

        // S = Q K^T (single term, plain bf16)
        float sc[8][4];
        #pragma unroll
        for (int nb = 0; nb < 8; nb++)
            #pragma unroll
            for (int i = 0; i < 4; i++) sc[nb][i] = 0.0f;

        #pragma unroll
        for (int ks = 0; ks < 4; ks++) {
            int kb = ks * 16;
            #pragma unroll
            for (int nb = 0; nb < 8; nb++) {
                int n = nb * 8 + g;
                const __nv_bfloat16* KH = Ksh + n * KSTR + kb + 2 * t;
                uint32_t bh[2] = { *(const uint32_t*)KH, *(const uint32_t*)(KH + 8) };
                mma16816(sc[nb], qh[ks], bh);
            }
        }

        // Mask (exactly -1e9, as in reference)
        #pragma unroll
        for (int nb = 0; nb < 8; nb++) {
            int c0 = nb * 8 + 2 * t;
            if (mS[c0])     { sc[nb][0] = -1e9f; sc[nb][2] = -1e9f; }
            if (mS[c0 + 1]) { sc[nb][1] = -1e9f; sc[nb][3] = -1e9f; }
        }

        // Row maxima (reduce over 4 t-threads)
        float rmg = -1e30f, rmg8 = -1e30f;
        #pragma unroll
        for (int nb = 0; nb < 8; nb++) {
            rmg  = fmaxf(rmg,  fmaxf(sc[nb][0], sc[nb][1]));
            rmg8 = fmaxf(rmg8, fmaxf(sc[nb][2], sc[nb][3]));
        }
        rmg  = fmaxf(rmg,  __shfl_xor_sync(0xffffffffu, rmg, 1));
        rmg  = fmaxf(rmg,  __shfl_xor_sync(0xffffffffu, rmg, 2));
        rmg8 = fmaxf(rmg8, __shfl_xor_sync(0xffffffffu, rmg8, 1));
        rmg8 = fmaxf(rmg8, __shfl_xor_sync(0xffffffffu, rmg8, 2));

        float mn_g = fmaxf(m_g, rmg), mn_g8 = fmaxf(m_g8, rmg8);
        float fct_g = exp_fma(m_g - mn_g), fct_g8 = exp_fma(m_g8 - mn_g8);
        m_g = mn_g; m_g8 = mn_g8;

        // P = exp(S - m) (FMA-pipe exp), hi/lo split, C-frag -> A-frag repack
        uint32_t pah[4][4], pal[4][4];
        float sl_g = 0.0f, sl_g8 = 0.0f;
        #pragma unroll
        for (int nb = 0; nb < 8; nb++) {
            float p0 = exp_fma(sc[nb][0] - mn_g);
            float p1 = exp_fma(sc[nb][1] - mn_g);
            float p2 = exp_fma(sc[nb][2] - mn_g8);
            float p3 = exp_fma(sc[nb][3] - mn_g8);
            sl_g += p0 + p1;  sl_g8 += p2 + p3;
            __nv_bfloat16 h0 = __float2bfloat16(p0), h1 = __float2bfloat16(p1);
            __nv_bfloat16 h2 = __float2bfloat16(p2), h3 = __float2bfloat16(p3);
            __nv_bfloat16 L0 = __float2bfloat16(p0 - __bfloat162float(h0));
            __nv_bfloat16 L1 = __float2bfloat16(p1 - __bfloat162float(h1));
            __nv_bfloat16 L2 = __float2bfloat16(p2 - __bfloat162float(h2));
            __nv_bfloat16 L3 = __float2bfloat16(p3 - __bfloat162float(h3));
            int kc = nb >> 1, hi = nb & 1;
            pah[kc][hi * 2 + 0] = bpack(h0, h1);
            pah[kc][hi * 2 + 1] = bpack(h2, h3);
            pal[kc][hi * 2 + 0] = bpack(L0, L1);
            pal[kc][hi * 2 + 1] = bpack(L2, L3);
        }
        sl_g  += __shfl_xor_sync(0xffffffffu, sl_g, 1);
        sl_g  += __shfl_xor_sync(0xffffffffu, sl_g, 2);
        sl_g8 += __shfl_xor_sync(0xffffffffu, sl_g8, 1);
        sl_g8 += __shfl_xor_sync(0xffffffffu, sl_g8, 2);
        l_g  = l_g  * fct_g  + sl_g;
        l_g8 = l_g8 * fct_g8 + sl_g8;

        // O = O*fct + P V (3-term split: ph*vh + ph*vl + pl*vh)
        #pragma unroll
        for (int nb = 0; nb < 8; nb++) {
            Ov[nb][0] *= fct_g;  Ov[nb][1] *= fct_g;
            Ov[nb][2] *= fct_g8; Ov[nb][3] *= fct_g8;
        }
        #pragma unroll
        for (int kc = 0; kc < 4; kc++) {
            int kb = kc * 16;
            #pragma unroll
            for (int nb = 0; nb < 8; nb++) {
                int n = nb * 8 + g;
                const __nv_bfloat16* VH = Vsh + n * KSTR + kb + 2 * t;
                const __nv_bfloat16* VL = Vsl + n * KSTR + kb + 2 * t;
                uint32_t vbh[2] = { *(const uint32_t*)VH, *(const uint32_t*)(VH + 8) };
                uint32_t vbl[2] = { *(const uint32_t*)VL, *(const uint32_t*)(VL + 8) };
                mma16816(Ov[nb], pah[kc], vbh);
                mma16816(Ov[nb], pah[kc], vbl);
                mma16816(Ov[nb], pal[kc], vbh);
            }
        }

        // Stage next chunk into the other buffer, then one barrier.
        if (c + 1 < 32) store_chunk((c + 1) & 1);
        __syncthreads();
    }

    // Epilogue
    float il_g = 1.0f / l_g, il_g8 = 1.0f / l_g8;
    float* po = out + ((size_t)b * SS + qrow) * DOUT;
    #pragma unroll
    for (int nb = 0; nb < 8; nb++) {
        int d = nb * 8 + 2 * t;
        float2 v0 = { Ov[nb][0] * il_g,  Ov[nb][1] * il_g  };
        float2 v1 = { Ov[nb][2] * il_g8, Ov[nb][3] * il_g8 };
        *(float2*)(po + d) = v0;
        *(float2*)(po + (size_t)8 * DOUT + d) = v1;
    }
}

// ---------------------------------------------------------------------------
extern "C" void kernel_launch(void* const* d_in, const int* in_sizes, int n_in,
                              void* d_out, int out_size)
{
    const float* seq = (const float*)d_in[0];
    const unsigned char* mask = (const unsigned char*)d_in[1];
    const float* Wq = (const float*)d_in[2];
    const float* bq = (const float*)d_in[3];
    const float* Wk = (const float*)d_in[4];
    const float* bk = (const float*)d_in[5];
    const float* Wv = (const float*)d_in[6];
    const float* bv = (const float*)d_in[7];
    float* out = (float*)d_out;

    w_convert<<<768, 256>>>(Wq, Wk, Wv);

    cudaFuncSetAttribute(proj_mma, cudaFuncAttributeMaxDynamicSharedMemorySize, PJ_SMEM);
    proj_mma<<<128, 256, PJ_SMEM>>>(seq, mask, bq, bk, bv);

    cudaFuncSetAttribute(attn_mma, cudaFuncAttributeMaxDynamicSharedMemorySize, ATT_SMEM);
    attn_mma<<<128, 256, ATT_SMEM>>>(out);
}